// round 16
// baseline (speedup 1.0000x reference)
#include <cuda_runtime.h>
#include <cuda_fp16.h>
#include <math.h>
#include <stdint.h>

#define G     128       // B*NV
#define HTOK  192
#define CH    512
#define NHD   8
#define HD    64
#define DFFC  2048
#define NTOK  24576     // G*HTOK
#define NELEM 12582912  // NTOK*CH

// ---------------- scratch (static device globals; allocation-free) ----------
__device__ float g_accb[NELEM];        // src + src2 (fp32)
__device__ float g_ps[192 * 512];
__device__ float g_pq[192 * 512];
__device__ float g_ps2[192 * 512];
__device__ float g_pq2[192 * 512];
__device__ float g_sc1[512];
__device__ float g_sh1[512];
__device__ float g_sc2[512];
__device__ float g_sh2[512];
__device__ float g_bf1[DFFC];          // folded bias FF1 (fp32)
__device__ float g_bf2[DFFC];          // folded bias FF2 (fp32)
__device__ float g_bc[512];            // combined second-layer bias
// fp16 buffers
__device__ __half g_qkh[NTOK * 1024];    // qk projection (half)
__device__ __half g_vh[NELEM];           // v projection (half)
__device__ __half g_q1h[NELEM];          // decayed q (half, head-major)
__device__ __half g_k1h[NELEM];          // decayed k
__device__ __half g_s1h[NELEM];          // normalized src
__device__ __half g_srch[NELEM];         // src
__device__ __half g_otr[NELEM];          // token-attn out (raw, half)
__device__ __half g_ohr[NELEM];          // hidden-attn out (raw, half)
__device__ __half g_hbh[NTOK * 4096];    // FF hidden (FF1 | FF2 columns)
__device__ __half g_wf1[DFFC * 512];     // folded W11
__device__ __half g_wf2[DFFC * 512];     // folded W21
__device__ __half g_wqk[1024 * 512];
__device__ __half g_wv[512 * 512];
__device__ __half g_w11[2048 * 512];
__device__ __half g_w21[2048 * 512];
__device__ __half g_wcat[512 * 4096];    // [W12 | W22] row-concat

__device__ __forceinline__ uint32_t smem_u32(const void* p) {
    uint32_t a;
    asm("{ .reg .u64 t; cvta.to.shared.u64 t, %1; cvt.u32.u64 %0, t; }"
        : "=r"(a) : "l"(p));
    return a;
}
__device__ __forceinline__ void mma_f16(float* c, const uint32_t* a, const uint32_t* b) {
    asm volatile(
        "mma.sync.aligned.m16n8k16.row.col.f32.f16.f16.f32 "
        "{%0,%1,%2,%3}, {%4,%5,%6,%7}, {%8,%9}, {%0,%1,%2,%3};"
        : "+f"(c[0]), "+f"(c[1]), "+f"(c[2]), "+f"(c[3])
        : "r"(a[0]), "r"(a[1]), "r"(a[2]), "r"(a[3]), "r"(b[0]), "r"(b[1]));
}
#define LDSM4(r, a)                                                            \
    asm volatile("ldmatrix.sync.aligned.m8n8.x4.shared.b16 {%0,%1,%2,%3}, [%4];" \
        : "=r"((r)[0]), "=r"((r)[1]), "=r"((r)[2]), "=r"((r)[3]) : "r"(a))
#define LDSM2(r, a)                                                            \
    asm volatile("ldmatrix.sync.aligned.m8n8.x2.shared.b16 {%0,%1}, [%2];"     \
        : "=r"((r)[0]), "=r"((r)[1]) : "r"(a))
#define LDSM4T(r, a)                                                           \
    asm volatile("ldmatrix.sync.aligned.m8n8.x4.trans.shared.b16 {%0,%1,%2,%3}, [%4];" \
        : "=r"((r)[0]), "=r"((r)[1]), "=r"((r)[2]), "=r"((r)[3]) : "r"(a))
#define LDSM2T(r, a)                                                           \
    asm volatile("ldmatrix.sync.aligned.m8n8.x2.trans.shared.b16 {%0,%1}, [%2];" \
        : "=r"((r)[0]), "=r"((r)[1]) : "r"(a))

// ============ fp16 mma GEMM, cp.async 3-stage: C = epi(A@B^T + bias) ========
// CTA tile 128x128, K-chunk 64, 8 warps (64x32), 2 CTAs/SM.
#define RSB 144                       // smem row stride bytes (64 halves + pad)
#define HSTG_BYTES (2 * 128 * RSB)    // 36864 per stage

struct Gp {
    const __half* A; const __half* B; const float* bias; void* C;
    const float* Xadd; float* ps; float* pq; int N; int ldc; int K; int gridN;
};

// EPI: 1 = GELU -> half, 3 = store half,
//      4 = fp32 store of acc+bias+Xadd, with fused per-chunk BN partial stats
template <int EPI>
__device__ __forceinline__ void gemm_body(const Gp p, int bid, char* hsm) {
    const int tid = threadIdx.x;
    const int wid = tid >> 5, lane = tid & 31;
    const int wm = wid >> 2, wn = wid & 3;
    const int g = lane >> 2, tig = lane & 3;

    int per = 8 * p.gridN;
    int grp = bid / per, rem = bid - grp * per;
    const int bm = (grp * 8 + (rem & 7)) * 128;
    const int bn = (rem >> 3) * 128;

    const __half* __restrict__ A = p.A;
    const __half* __restrict__ B = p.B;
    const int K = p.K;
    const uint32_t sbase = smem_u32(hsm);
    const int CCH = K >> 6;

    const int c_row = tid >> 3;
    const int c_cq = tid & 7;
    #define CPYH(c, s) do {                                                     \
        int _kc = (c) << 6;                                                     \
        uint32_t _sa = sbase + (uint32_t)(s) * HSTG_BYTES;                      \
        _Pragma("unroll")                                                       \
        for (int _i = 0; _i < 4; _i++) {                                        \
            int _row = c_row + _i * 32;                                         \
            uint32_t _off = (uint32_t)_row * RSB + (uint32_t)c_cq * 16u;        \
            const __half* _ga = A + (size_t)(bm + _row) * K + _kc + c_cq * 8;   \
            asm volatile("cp.async.cg.shared.global [%0], [%1], 16;"            \
                         :: "r"(_sa + _off), "l"(_ga));                         \
            const __half* _gb = B + (size_t)(bn + _row) * K + _kc + c_cq * 8;   \
            asm volatile("cp.async.cg.shared.global [%0], [%1], 16;"            \
                         :: "r"(_sa + 18432u + _off), "l"(_gb));                \
        }                                                                       \
    } while (0)

    CPYH(0, 0);
    asm volatile("cp.async.commit_group;" ::: "memory");
    CPYH(1, 1);
    asm volatile("cp.async.commit_group;" ::: "memory");

    float acc[4][4][4];
    #pragma unroll
    for (int mt = 0; mt < 4; mt++)
        #pragma unroll
        for (int nt = 0; nt < 4; nt++)
            #pragma unroll
            for (int i = 0; i < 4; i++) acc[mt][nt][i] = 0.f;

    asm volatile("cp.async.wait_group 1;" ::: "memory");
    __syncthreads();

    const int lr = lane & 7, sel = lane >> 3;
    const uint32_t aoff =
        (uint32_t)(wm * 64 + (sel & 1) * 8 + lr) * RSB + (uint32_t)((sel >> 1) * 8) * 2;
    const uint32_t boff =
        (uint32_t)(wn * 32 + lr) * RSB + (uint32_t)((sel & 1) * 8) * 2;

    for (int c = 0; c < CCH; c++) {
        int rs = c % 3;
        if (c + 2 < CCH) {
            int ws = rs + 2; if (ws >= 3) ws -= 3;
            CPYH(c + 2, ws);
        }
        asm volatile("cp.async.commit_group;" ::: "memory");

        uint32_t sA = sbase + (uint32_t)rs * HSTG_BYTES;
        uint32_t sB = sA + 18432u;
        #pragma unroll
        for (int kt = 0; kt < 4; kt++) {
            uint32_t af[4][4], bf[4][2];
            #pragma unroll
            for (int mt = 0; mt < 4; mt++)
                LDSM4(af[mt], sA + aoff + (uint32_t)(mt * 16) * RSB + (uint32_t)kt * 32u);
            #pragma unroll
            for (int nt = 0; nt < 4; nt++)
                LDSM2(bf[nt], sB + boff + (uint32_t)(nt * 8) * RSB + (uint32_t)kt * 32u);
            #pragma unroll
            for (int mt = 0; mt < 4; mt++)
                #pragma unroll
                for (int nt = 0; nt < 4; nt++)
                    mma_f16(acc[mt][nt], af[mt], bf[nt]);
        }
        asm volatile("cp.async.wait_group 1;" ::: "memory");
        __syncthreads();
    }
    #undef CPYH

    const int ldc = p.ldc;
    if (EPI == 1 || EPI == 3) {
        #pragma unroll
        for (int mt = 0; mt < 4; mt++) {
            int m0 = bm + wm * 64 + mt * 16 + g;
            #pragma unroll
            for (int nt = 0; nt < 4; nt++) {
                int n0 = bn + wn * 32 + nt * 8 + tig * 2;
                float b0 = p.bias[n0], b1 = p.bias[n0 + 1];
                float v00 = acc[mt][nt][0] + b0;
                float v01 = acc[mt][nt][1] + b1;
                float v10 = acc[mt][nt][2] + b0;
                float v11 = acc[mt][nt][3] + b1;
                if (EPI == 1) {
                    v00 = 0.5f * v00 * (1.0f + erff(v00 * 0.70710678118654752f));
                    v01 = 0.5f * v01 * (1.0f + erff(v01 * 0.70710678118654752f));
                    v10 = 0.5f * v10 * (1.0f + erff(v10 * 0.70710678118654752f));
                    v11 = 0.5f * v11 * (1.0f + erff(v11 * 0.70710678118654752f));
                }
                __half* Ch = (__half*)p.C;
                *reinterpret_cast<__half2*>(Ch + (size_t)m0 * ldc + n0) =
                    __floats2half2_rn(v00, v01);
                *reinterpret_cast<__half2*>(Ch + (size_t)(m0 + 8) * ldc + n0) =
                    __floats2half2_rn(v10, v11);
            }
        }
    } else {  // EPI == 4: fp32 store of acc + bias + Xadd, fused BN partials
        float* ssum = reinterpret_cast<float*>(hsm);      // [16][130]
        float* ssq = ssum + 16 * 130;                     // [16][130]
        #pragma unroll
        for (int nt = 0; nt < 4; nt++) {
            int n0 = bn + wn * 32 + nt * 8 + tig * 2;
            float b0 = p.bias[n0], b1 = p.bias[n0 + 1];
            float cs0 = 0.f, cs1 = 0.f, cq0 = 0.f, cq1 = 0.f;
            #pragma unroll
            for (int mt = 0; mt < 4; mt++) {
                int m0 = bm + wm * 64 + mt * 16 + g;
                float v00 = acc[mt][nt][0] + b0;
                float v01 = acc[mt][nt][1] + b1;
                float v10 = acc[mt][nt][2] + b0;
                float v11 = acc[mt][nt][3] + b1;
                float2 s0 = *reinterpret_cast<const float2*>(p.Xadd + (size_t)m0 * ldc + n0);
                float2 s1 = *reinterpret_cast<const float2*>(p.Xadd + (size_t)(m0 + 8) * ldc + n0);
                v00 += s0.x; v01 += s0.y;
                v10 += s1.x; v11 += s1.y;
                *reinterpret_cast<float2*>((float*)p.C + (size_t)m0 * ldc + n0) =
                    make_float2(v00, v01);
                *reinterpret_cast<float2*>((float*)p.C + (size_t)(m0 + 8) * ldc + n0) =
                    make_float2(v10, v11);
                cs0 += v00 + v10; cs1 += v01 + v11;
                cq0 += v00 * v00 + v10 * v10;
                cq1 += v01 * v01 + v11 * v11;
            }
            int contrib = wm * 8 + g;               // 0..15
            int lc = wn * 32 + nt * 8 + tig * 2;    // local col 0..127
            *reinterpret_cast<float2*>(ssum + contrib * 130 + lc) = make_float2(cs0, cs1);
            *reinterpret_cast<float2*>(ssq + contrib * 130 + lc) = make_float2(cq0, cq1);
        }
        __syncthreads();
        if (tid < 128) {
            float s = 0.f, q = 0.f;
            #pragma unroll
            for (int k = 0; k < 16; k++) {
                s += ssum[k * 130 + tid];
                q += ssq[k * 130 + tid];
            }
            int idx = (bm >> 7) * 512 + bn + tid;
            p.ps[idx] = s;
            p.pq[idx] = q;
        }
    }
}

template <int EPI>
__global__ void __launch_bounds__(256, 2) hgemm_k(Gp p) {
    extern __shared__ char hsm[];
    gemm_body<EPI>(p, blockIdx.x, hsm);
}

template <int EPI>
__global__ void __launch_bounds__(256, 2) hgemm_dual_k(Gp p0, Gp p1, int split) {
    extern __shared__ char hsm[];
    if ((int)blockIdx.x < split) gemm_body<EPI>(p0, blockIdx.x, hsm);
    else                         gemm_body<EPI>(p1, blockIdx.x - split, hsm);
}

// -------- fused weight convert + combined bias: last block does bias add ----
__global__ void wcvt_k(const float* __restrict__ qkw, const float* __restrict__ vw,
                       const float* __restrict__ w11, const float* __restrict__ w21,
                       const float* __restrict__ w12, const float* __restrict__ w22,
                       __half* __restrict__ dqk, __half* __restrict__ dv,
                       __half* __restrict__ d11, __half* __restrict__ d21,
                       __half* __restrict__ dcat,
                       const float* __restrict__ b12, const float* __restrict__ b22,
                       float* __restrict__ bc) {
    if (blockIdx.x >= 4864) {
        int j = (blockIdx.x - 4864) * 256 + threadIdx.x;
        if (j < 512) bc[j] = b12[j] + b22[j];
        return;
    }
    int i = blockIdx.x * blockDim.x + threadIdx.x;  // float4 index, < 1245184
    const float* s; __half* d; int sof, dof;
    if (i < 131072)       { s = qkw; d = dqk; sof = i; dof = sof; }
    else if (i < 196608)  { s = vw;  d = dv;  sof = i - 131072; dof = sof; }
    else if (i < 458752)  { s = w11; d = d11; sof = i - 196608; dof = sof; }
    else if (i < 720896)  { s = w21; d = d21; sof = i - 458752; dof = sof; }
    else if (i < 983040)  { s = w12; d = dcat; sof = i - 720896;
                            dof = (sof >> 9) * 1024 + (sof & 511); }
    else                  { s = w22; d = dcat; sof = i - 983040;
                            dof = (sof >> 9) * 1024 + 512 + (sof & 511); }
    float4 v = reinterpret_cast<const float4*>(s)[sof];
    __half2* yp = reinterpret_cast<__half2*>(d + (size_t)dof * 4);
    yp[0] = __floats2half2_rn(v.x, v.y);
    yp[1] = __floats2half2_rn(v.z, v.w);
}

// ------- fold BN into FF first-layer weight: Wo = W*sc, biaso = b + W@sh ----
__global__ void wfold2_k(const __half* __restrict__ W11, const float* __restrict__ b11,
                         const __half* __restrict__ W21, const float* __restrict__ b21,
                         const float* __restrict__ sc1, const float* __restrict__ sh1,
                         const float* __restrict__ sc2, const float* __restrict__ sh2,
                         __half* __restrict__ Wo1, float* __restrict__ bo1,
                         __half* __restrict__ Wo2, float* __restrict__ bo2) {
    int blk = blockIdx.x;
    const __half* W; const float* bias; const float* sc; const float* sh;
    __half* Wo; float* bo;
    int row = (blk & 255) * 8 + (threadIdx.x >> 5);
    if (blk < 256) { W = W11; bias = b11; sc = sc1; sh = sh1; Wo = Wo1; bo = bo1; }
    else           { W = W21; bias = b21; sc = sc2; sh = sh2; Wo = Wo2; bo = bo2; }
    int lane = threadIdx.x & 31;
    const __half2* wr = reinterpret_cast<const __half2*>(W + (size_t)row * 512);
    __half2* wo = reinterpret_cast<__half2*>(Wo + (size_t)row * 512);
    float dot = 0.f;
    #pragma unroll
    for (int k = 0; k < 8; k++) {
        int j = lane + k * 32;
        float2 wf = __half22float2(wr[j]);
        dot += sh[2 * j] * wf.x + sh[2 * j + 1] * wf.y;
        wo[j] = __floats2half2_rn(wf.x * sc[2 * j], wf.y * sc[2 * j + 1]);
    }
    #pragma unroll
    for (int o = 16; o > 0; o >>= 1) dot += __shfl_xor_sync(0xffffffffu, dot, o);
    if (lane == 0) bo[row] = bias[row] + dot;
}

// ------------- fused: src -> srch (half) + l2-normalized src (half) ---------
__global__ void l2norm_src_k(const float* __restrict__ X,
                             __half* __restrict__ Yn, __half* __restrict__ Yr) {
    __shared__ float red[4];
    int row = blockIdx.x;
    int tid = threadIdx.x;  // 128
    const float4* xp = reinterpret_cast<const float4*>(X + (size_t)row * CH);
    float4 v = xp[tid];
    float ss = v.x * v.x + v.y * v.y + v.z * v.z + v.w * v.w;
    #pragma unroll
    for (int o = 16; o > 0; o >>= 1) ss += __shfl_xor_sync(0xffffffffu, ss, o);
    if ((tid & 31) == 0) red[tid >> 5] = ss;
    __syncthreads();
    float rn = rsqrtf(red[0] + red[1] + red[2] + red[3]);
    __half2* yr = reinterpret_cast<__half2*>(Yr + (size_t)row * CH + tid * 4);
    yr[0] = __floats2half2_rn(v.x, v.y);
    yr[1] = __floats2half2_rn(v.z, v.w);
    __half2* yn = reinterpret_cast<__half2*>(Yn + (size_t)row * CH + tid * 4);
    yn[0] = __floats2half2_rn(v.x * rn, v.y * rn);
    yn[1] = __floats2half2_rn(v.z * rn, v.w * rn);
}

// ---------------- exponential-decay scan (half2 in -> half2 out) ------------
__global__ void decay_k(const __half* __restrict__ QK, const float* __restrict__ alpha,
                        __half* __restrict__ Q1, __half* __restrict__ K1) {
    int g = blockIdx.x;      // 0..127
    int which = blockIdx.y;  // 0=q, 1=k
    int ch2 = threadIdx.x;   // 0..255 (pairs of channels)
    int d0 = (2 * ch2) & 63;
    int nh = (2 * ch2) >> 6;
    float a0 = 1.f / (1.f + expf(-alpha[d0]));
    float a1 = 1.f / (1.f + expf(-alpha[d0 + 1]));
    float l2r0 = log2f(1.f - a0);
    float l2r1 = log2f(1.f - a1);
    const __half2* x = reinterpret_cast<const __half2*>(
        QK + (size_t)g * (HTOK * 1024) + which * 512) + ch2;
    __half2* y = reinterpret_cast<__half2*>(
        (which ? K1 : Q1) + (size_t)g * (NHD * HTOK * HD) +
        (size_t)nh * (HTOK * HD) + d0);
    float z0 = 0.f, z1 = 0.f;
    for (int t = 0; t < HTOK; ++t) {
        float2 xv = __half22float2(x[(size_t)t * 512]);
        z0 = fmaf(xv.x, exp2f((float)t * l2r0), z0);
        z1 = fmaf(xv.y, exp2f((float)t * l2r1), z1);
        y[(size_t)t * 32] = __floats2half2_rn(
            a0 * exp2f((float)(HTOK - 1 - t) * l2r0) * z0,
            a1 * exp2f((float)(HTOK - 1 - t) * l2r1) * z1);
    }
}

// ============ token attention, fp16 mma: per-head 192x192x64 ================
#define SRF 196    // Sf float stride (784B rows)
#define TOK_SMEM 206592

__global__ void __launch_bounds__(256, 1) tok_attn_mma_k(
    const __half* __restrict__ Q1, const __half* __restrict__ K1,
    const __half* __restrict__ V, __half* __restrict__ O) {
    extern __shared__ char smc[];
    const uint32_t sb = smem_u32(smc);
    const uint32_t sQ = sb, sK = sb + 27648u, sS = sb + 55296u;
    float* Sf = reinterpret_cast<float*>(smc + 55296);
    float* linv = reinterpret_cast<float*>(smc + 205824);
    const int head = blockIdx.x;
    const int g = head >> 3, nh = head & 7;
    const int tid = threadIdx.x, wid = tid >> 5, lane = tid & 31;
    const int wm = wid >> 1, wn = wid & 1;        // 4m x 2n
    const int gq = lane >> 2, tg = lane & 3;
    const int lr = lane & 7, sel = lane >> 3;

    {
        const __half* Qg = Q1 + (size_t)head * 12288;
        const __half* Kg = K1 + (size_t)head * 12288;
        #pragma unroll
        for (int i = 0; i < 6; i++) {
            int idx = i * 256 + tid;
            int row = idx >> 3, cq = idx & 7;
            uint32_t off = (uint32_t)row * RSB + (uint32_t)cq * 16u;
            asm volatile("cp.async.cg.shared.global [%0], [%1], 16;"
                         :: "r"(sQ + off), "l"(Qg + row * 64 + cq * 8));
            asm volatile("cp.async.cg.shared.global [%0], [%1], 16;"
                         :: "r"(sK + off), "l"(Kg + row * 64 + cq * 8));
        }
        asm volatile("cp.async.commit_group;" ::: "memory");
        asm volatile("cp.async.wait_group 0;" ::: "memory");
    }
    __syncthreads();

    // S = Q1 @ K1^T : warp tile 48x96
    {
        float acc[3][12][4];
        #pragma unroll
        for (int mt = 0; mt < 3; mt++)
            #pragma unroll
            for (int nt = 0; nt < 12; nt++)
                #pragma unroll
                for (int i = 0; i < 4; i++) acc[mt][nt][i] = 0.f;
        const int m0w = wm * 48, n0w = wn * 96;
        #pragma unroll
        for (int kt = 0; kt < 4; kt++) {
            uint32_t af[3][4], bf[12][2];
            #pragma unroll
            for (int mt = 0; mt < 3; mt++)
                LDSM4(af[mt], sQ + (uint32_t)(m0w + mt * 16 + (sel & 1) * 8 + lr) * RSB +
                              (uint32_t)(kt * 16 + (sel >> 1) * 8) * 2u);
            #pragma unroll
            for (int nt = 0; nt < 12; nt++)
                LDSM2(bf[nt], sK + (uint32_t)(n0w + nt * 8 + lr) * RSB +
                              (uint32_t)(kt * 16 + (sel & 1) * 8) * 2u);
            #pragma unroll
            for (int mt = 0; mt < 3; mt++)
                #pragma unroll
                for (int nt = 0; nt < 12; nt++)
                    mma_f16(acc[mt][nt], af[mt], bf[nt]);
        }
        #pragma unroll
        for (int mt = 0; mt < 3; mt++) {
            int r0 = m0w + mt * 16 + gq;
            #pragma unroll
            for (int nt = 0; nt < 12; nt++) {
                int c0 = n0w + nt * 8 + tg * 2;
                Sf[r0 * SRF + c0]           = acc[mt][nt][0] * 8.0f;
                Sf[r0 * SRF + c0 + 1]       = acc[mt][nt][1] * 8.0f;
                Sf[(r0 + 8) * SRF + c0]     = acc[mt][nt][2] * 8.0f;
                Sf[(r0 + 8) * SRF + c0 + 1] = acc[mt][nt][3] * 8.0f;
            }
        }
    }
    __syncthreads();

    // V load (half, direct cp.async) into Q1 region; overlaps with softmax
    {
        const __half* Vg = V + (size_t)(g * 192) * 512 + nh * 64;
        #pragma unroll
        for (int i = 0; i < 6; i++) {
            int idx = i * 256 + tid;
            int row = idx >> 3, cq = idx & 7;
            asm volatile("cp.async.cg.shared.global [%0], [%1], 16;"
                         :: "r"(sQ + (uint32_t)row * RSB + (uint32_t)cq * 16u),
                            "l"(Vg + (size_t)row * 512 + cq * 8));
        }
        asm volatile("cp.async.commit_group;" ::: "memory");
    }
    // softmax over rows (tid < 192)
    if (tid < 192) {
        float* row = Sf + tid * SRF;
        float mx = -1e30f;
        #pragma unroll 8
        for (int j = 0; j < 192; j += 4) {
            float4 v = *reinterpret_cast<const float4*>(row + j);
            mx = fmaxf(mx, fmaxf(fmaxf(v.x, v.y), fmaxf(v.z, v.w)));
        }
        float sum = 0.f;
        __half2* ph = reinterpret_cast<__half2*>(row);
        #pragma unroll 8
        for (int j = 0; j < 192; j += 4) {
            float4 v = *reinterpret_cast<const float4*>(row + j);
            float e0 = __expf(v.x - mx), e1 = __expf(v.y - mx);
            float e2 = __expf(v.z - mx), e3 = __expf(v.w - mx);
            sum += (e0 + e1) + (e2 + e3);
            ph[j >> 1] = __floats2half2_rn(e0, e1);
            ph[(j >> 1) + 1] = __floats2half2_rn(e2, e3);
        }
        linv[tid] = 1.0f / sum;
    }
    asm volatile("cp.async.wait_group 0;" ::: "memory");
    __syncthreads();

    // O = P @ V : warp tile 48x32 over k=192
    {
        float acc[3][4][4];
        #pragma unroll
        for (int mt = 0; mt < 3; mt++)
            #pragma unroll
            for (int nt = 0; nt < 4; nt++)
                #pragma unroll
                for (int i = 0; i < 4; i++) acc[mt][nt][i] = 0.f;
        const int m0 = wm * 48, n0 = wn * 32;
        #pragma unroll
        for (int kt = 0; kt < 12; kt++) {
            uint32_t af[3][4], bf[4][2];
            #pragma unroll
            for (int mt = 0; mt < 3; mt++)
                LDSM4(af[mt], sS + (uint32_t)(m0 + mt * 16 + (sel & 1) * 8 + lr) * 784u +
                              (uint32_t)(kt * 16 + (sel >> 1) * 8) * 2u);
            #pragma unroll
            for (int nt = 0; nt < 4; nt++)
                LDSM2T(bf[nt], sQ + (uint32_t)(kt * 16 + (sel & 1) * 8 + lr) * RSB +
                               (uint32_t)(n0 + nt * 8) * 2u);
            #pragma unroll
            for (int mt = 0; mt < 3; mt++)
                #pragma unroll
                for (int nt = 0; nt < 4; nt++)
                    mma_f16(acc[mt][nt], af[mt], bf[nt]);
        }
        __half* Og = O + (size_t)head * 12288;
        #pragma unroll
        for (int mt = 0; mt < 3; mt++) {
            int r = m0 + mt * 16 + gq;
            float i0 = linv[r], i1 = linv[r + 8];
            #pragma unroll
            for (int nt = 0; nt < 4; nt++) {
                int c = n0 + nt * 8 + tg * 2;
                *reinterpret_cast<__half2*>(Og + r * 64 + c) =
                    __floats2half2_rn(acc[mt][nt][0] * i0, acc[mt][nt][1] * i0);
                *reinterpret_cast<__half2*>(Og + (r + 8) * 64 + c) =
                    __floats2half2_rn(acc[mt][nt][2] * i1, acc[mt][nt][3] * i1);
            }
        }
    }
}

// ============ hidden attention, fp16 mma: per-head 64x64 over 192 ===========
#define HID_SMEM 109824

__global__ void __launch_bounds__(256, 2) hid_attn_mma_k(
    const __half* __restrict__ QK, const __half* __restrict__ V,
    __half* __restrict__ O) {
    extern __shared__ char smc[];
    const uint32_t sb = smem_u32(smc);
    const uint32_t sQ = sb, sK = sb + 27648u, sV = sb + 55296u, sP = sb + 100352u;
    float* S2f = reinterpret_cast<float*>(smc + 82944);
    float* linv2 = reinterpret_cast<float*>(smc + 109568);
    const int head = blockIdx.x;
    const int g = head >> 3, nh = head & 7;
    const int tid = threadIdx.x, wid = tid >> 5, lane = tid & 31;
    const int gq = lane >> 2, tg = lane & 3;
    const int lr = lane & 7, sel = lane >> 3;

    {
        const __half* Qg = QK + (size_t)(g * 192) * 1024 + nh * 64;
        const __half* Kg = Qg + 512;
        const __half* Vg = V + (size_t)(g * 192) * 512 + nh * 64;
        #pragma unroll
        for (int i = 0; i < 6; i++) {
            int idx = i * 256 + tid;
            int row = idx >> 3, cq = idx & 7;
            uint32_t off = (uint32_t)row * RSB + (uint32_t)cq * 16u;
            asm volatile("cp.async.cg.shared.global [%0], [%1], 16;"
                         :: "r"(sQ + off), "l"(Qg + (size_t)row * 1024 + cq * 8));
            asm volatile("cp.async.cg.shared.global [%0], [%1], 16;"
                         :: "r"(sK + off), "l"(Kg + (size_t)row * 1024 + cq * 8));
            asm volatile("cp.async.cg.shared.global [%0], [%1], 16;"
                         :: "r"(sV + off), "l"(Vg + (size_t)row * 512 + cq * 8));
        }
        asm volatile("cp.async.commit_group;" ::: "memory");
        asm volatile("cp.async.wait_group 0;" ::: "memory");
    }
    __syncthreads();

    // S2 = Q^T @ K (64x64 over a=192)
    {
        float acc[2][2][4];
        #pragma unroll
        for (int mt = 0; mt < 2; mt++)
            #pragma unroll
            for (int nt = 0; nt < 2; nt++)
                #pragma unroll
                for (int i = 0; i < 4; i++) acc[mt][nt][i] = 0.f;
        const int m0 = (wid >> 2) * 32, n0 = (wid & 3) * 16;
        #pragma unroll
        for (int kt = 0; kt < 12; kt++) {
            uint32_t af[2][4], bf[2][2];
            #pragma unroll
            for (int mt = 0; mt < 2; mt++)
                LDSM4T(af[mt], sQ + (uint32_t)(kt * 16 + (sel >> 1) * 8 + lr) * RSB +
                               (uint32_t)(m0 + mt * 16 + (sel & 1) * 8) * 2u);
            #pragma unroll
            for (int nt = 0; nt < 2; nt++)
                LDSM2T(bf[nt], sK + (uint32_t)(kt * 16 + (sel & 1) * 8 + lr) * RSB +
                               (uint32_t)(n0 + nt * 8) * 2u);
            #pragma unroll
            for (int mt = 0; mt < 2; mt++)
                #pragma unroll
                for (int nt = 0; nt < 2; nt++)
                    mma_f16(acc[mt][nt], af[mt], bf[nt]);
        }
        #pragma unroll
        for (int mt = 0; mt < 2; mt++) {
            int r0 = m0 + mt * 16 + gq;
            #pragma unroll
            for (int nt = 0; nt < 2; nt++) {
                int c0 = n0 + nt * 8 + tg * 2;
                S2f[r0 * 68 + c0]           = acc[mt][nt][0] * 13.856406460551018f;
                S2f[r0 * 68 + c0 + 1]       = acc[mt][nt][1] * 13.856406460551018f;
                S2f[(r0 + 8) * 68 + c0]     = acc[mt][nt][2] * 13.856406460551018f;
                S2f[(r0 + 8) * 68 + c0 + 1] = acc[mt][nt][3] * 13.856406460551018f;
            }
        }
    }
    __syncthreads();

    if (tid < 64) {
        float* row = S2f + tid * 68;
        float mx = -1e30f;
        #pragma unroll
        for (int j = 0; j < 64; j += 4) {
            float4 v = *reinterpret_cast<const float4*>(row + j);
            mx = fmaxf(mx, fmaxf(fmaxf(v.x, v.y), fmaxf(v.z, v.w)));
        }
        float sum = 0.f;
        __half2* ph = reinterpret_cast<__half2*>(smc + 100352 + tid * RSB);
        #pragma unroll
        for (int j = 0; j < 64; j += 4) {
            float4 v = *reinterpret_cast<const float4*>(row + j);
            float e0 = __expf(v.x - mx), e1 = __expf(v.y - mx);
            float e2 = __expf(v.z - mx), e3 = __expf(v.w - mx);
            sum += (e0 + e1) + (e2 + e3);
            ph[j >> 1] = __floats2half2_rn(e0, e1);
            ph[(j >> 1) + 1] = __floats2half2_rn(e2, e3);
        }
        linv2[tid] = 1.0f / sum;
    }
    __syncthreads();

    // O2 = V @ P2^T (192x64 over f=64)
    {
        float acc[3][4][4];
        #pragma unroll
        for (int mt = 0; mt < 3; mt++)
            #pragma unroll
            for (int nt = 0; nt < 4; nt++)
                #pragma unroll
                for (int i = 0; i < 4; i++) acc[mt][nt][i] = 0.f;
        const int m0 = (wid >> 1) * 48, n0 = (wid & 1) * 32;
        #pragma unroll
        for (int kt = 0; kt < 4; kt++) {
            uint32_t af[3][4], bf[4][2];
            #pragma unroll
            for (int mt = 0; mt < 3; mt++)
                LDSM4(af[mt], sV + (uint32_t)(m0 + mt * 16 + (sel & 1) * 8 + lr) * RSB +
                              (uint32_t)(kt * 16 + (sel >> 1) * 8) * 2u);
            #pragma unroll
            for (int nt = 0; nt < 4; nt++)
                LDSM2(bf[nt], sP + (uint32_t)(n0 + nt * 8 + lr) * RSB +
                              (uint32_t)(kt * 16 + (sel & 1) * 8) * 2u);
            #pragma unroll
            for (int mt = 0; mt < 3; mt++)
                #pragma unroll
                for (int nt = 0; nt < 4; nt++)
                    mma_f16(acc[mt][nt], af[mt], bf[nt]);
        }
        __half* Og = O + (size_t)head * 12288;
        #pragma unroll
        for (int mt = 0; mt < 3; mt++) {
            int r = m0 + mt * 16 + gq;
            #pragma unroll
            for (int nt = 0; nt < 4; nt++) {
                int c = n0 + nt * 8 + tg * 2;
                float i0 = linv2[c], i1 = linv2[c + 1];
                *reinterpret_cast<__half2*>(Og + r * 64 + c) =
                    __floats2half2_rn(acc[mt][nt][0] * i0, acc[mt][nt][1] * i1);
                *reinterpret_cast<__half2*>(Og + (r + 8) * 64 + c) =
                    __floats2half2_rn(acc[mt][nt][2] * i0, acc[mt][nt][3] * i1);
            }
        }
    }
}

// ---------------- BatchNorm (train-mode batch stats) ------------------------
__global__ void bn_partial2_h_k(const __half* __restrict__ X1, const __half* __restrict__ X2,
                                float* __restrict__ ps, float* __restrict__ pq,
                                float* __restrict__ ps2, float* __restrict__ pq2) {
    int chunk = blockIdx.x;
    int ch = threadIdx.x;
    const __half* X = blockIdx.y ? X2 : X1;
    float* psum = blockIdx.y ? ps2 : ps;
    float* psq = blockIdx.y ? pq2 : pq;
    const __half* p = X + (size_t)chunk * 128 * CH + ch;
    float s = 0.f, q = 0.f;
    for (int r = 0; r < 128; r++) {
        float v = __half2float(p[(size_t)r * CH]);
        s += v; q = fmaf(v, v, q);
    }
    psum[chunk * CH + ch] = s;
    psq[chunk * CH + ch] = q;
}

__device__ __forceinline__ void bn_final_body(
    const float* psum, const float* psq, const float* gamma, const float* beta,
    float* scale, float* shift, int ch, int lane) {
    float s = 0.f, q = 0.f;
    for (int c = lane; c < 192; c += 32) {
        s += psum[c * CH + ch];
        q += psq[c * CH + ch];
    }
    #pragma unroll
    for (int o = 16; o > 0; o >>= 1) {
        s += __shfl_xor_sync(0xffffffffu, s, o);
        q += __shfl_xor_sync(0xffffffffu, q, o);
    }
    if (lane == 0) {
        float mu = s * (1.0f / NTOK);
        float var = q * (1.0f / NTOK) - mu * mu;
        float sc = gamma[ch] * rsqrtf(var + 1e-5f);
        scale[ch] = sc;
        shift[ch] = beta[ch] - mu * sc;
    }
}

__global__ void bn_final_k(const float* __restrict__ psum, const float* __restrict__ psq,
                           const float* __restrict__ gamma, const float* __restrict__ beta,
                           float* __restrict__ scale, float* __restrict__ shift) {
    int ch = blockIdx.x * 8 + (threadIdx.x >> 5);
    bn_final_body(psum, psq, gamma, beta, scale, shift, ch, threadIdx.x & 31);
}

__global__ void bn_final2_k(const float* __restrict__ ps, const float* __restrict__ pq,
                            const float* __restrict__ g1, const float* __restrict__ b1,
                            float* __restrict__ sc1v, float* __restrict__ sh1v,
                            const float* __restrict__ ps2, const float* __restrict__ pq2,
                            const float* __restrict__ g2, const float* __restrict__ b2,
                            float* __restrict__ sc2v, float* __restrict__ sh2v) {
    int blk = blockIdx.x;
    int ch = (blk & 63) * 8 + (threadIdx.x >> 5);
    int lane = threadIdx.x & 31;
    if (blk < 64) bn_final_body(ps, pq, g1, b1, sc1v, sh1v, ch, lane);
    else          bn_final_body(ps2, pq2, g2, b2, sc2v, sh2v, ch, lane);
}

__global__ void bn_apply1_k(float* __restrict__ Y, const float* __restrict__ X,
                            const float* __restrict__ scale, const float* __restrict__ shift) {
    int i = blockIdx.x * blockDim.x + threadIdx.x;
    int ch4 = (i & 127) << 2;
    float4 x = reinterpret_cast<const float4*>(X)[i];
    x.x = fmaf(x.x, scale[ch4 + 0], shift[ch4 + 0]);
    x.y = fmaf(x.y, scale[ch4 + 1], shift[ch4 + 1]);
    x.z = fmaf(x.z, scale[ch4 + 2], shift[ch4 + 2]);
    x.w = fmaf(x.w, scale[ch4 + 3], shift[ch4 + 3]);
    reinterpret_cast<float4*>(Y)[i] = x;
}

// ---------------- driver ----------------------------------------------------
extern "C" void kernel_launch(void* const* d_in, const int* in_sizes, int n_in,
                              void* d_out, int out_size) {
    const float* src    = (const float*)d_in[0];
    const float* qk_w   = (const float*)d_in[1];
    const float* qk_b   = (const float*)d_in[2];
    const float* v_w    = (const float*)d_in[3];
    const float* v_b    = (const float*)d_in[4];
    const float* alpha  = (const float*)d_in[5];
    const float* g_pre1 = (const float*)d_in[6];
    const float* b_pre1 = (const float*)d_in[7];
    const float* g_pre2 = (const float*)d_in[8];
    const float* b_pre2 = (const float*)d_in[9];
    const float* f1w1   = (const float*)d_in[10];
    const float* f1b1   = (const float*)d_in[11];
    const float* f1w2   = (const float*)d_in[12];
    const float* f1b2   = (const float*)d_in[13];
    const float* f2w1   = (const float*)d_in[14];
    const float* f2b1   = (const float*)d_in[15];
    const float* f2w2   = (const float*)d_in[16];
    const float* f2b2   = (const float*)d_in[17];
    const float* g_attn = (const float*)d_in[18];
    const float* b_attn = (const float*)d_in[19];
    float* out = (float*)d_out;

    float *ACC, *PS, *PQ, *PS2, *PQ2, *SC1, *SH1, *SC2, *SH2, *BF1, *BF2, *BC;
    __half *QKh, *Vh, *Q1h, *K1h, *S1h, *SRCh, *OTr, *OHr, *HBh, *WF1, *WF2;
    __half *WQK, *WV, *W11, *W21, *WCAT;
    cudaGetSymbolAddress((void**)&ACC, g_accb);
    cudaGetSymbolAddress((void**)&PS,  g_ps);
    cudaGetSymbolAddress((void**)&PQ,  g_pq);
    cudaGetSymbolAddress((void**)&PS2, g_ps2);
    cudaGetSymbolAddress((void**)&PQ2, g_pq2);
    cudaGetSymbolAddress((void**)&SC1, g_sc1);
    cudaGetSymbolAddress((void**)&SH1, g_sh1);
    cudaGetSymbolAddress((void**)&SC2, g_sc2);
    cudaGetSymbolAddress((void**)&SH2, g_sh2);
    cudaGetSymbolAddress((void**)&BF1, g_bf1);
    cudaGetSymbolAddress((void**)&BF2, g_bf2);
    cudaGetSymbolAddress((void**)&BC,  g_bc);
    cudaGetSymbolAddress((void**)&QKh,  g_qkh);
    cudaGetSymbolAddress((void**)&Vh,   g_vh);
    cudaGetSymbolAddress((void**)&Q1h,  g_q1h);
    cudaGetSymbolAddress((void**)&K1h,  g_k1h);
    cudaGetSymbolAddress((void**)&S1h,  g_s1h);
    cudaGetSymbolAddress((void**)&SRCh, g_srch);
    cudaGetSymbolAddress((void**)&OTr,  g_otr);
    cudaGetSymbolAddress((void**)&OHr,  g_ohr);
    cudaGetSymbolAddress((void**)&HBh,  g_hbh);
    cudaGetSymbolAddress((void**)&WF1,  g_wf1);
    cudaGetSymbolAddress((void**)&WF2,  g_wf2);
    cudaGetSymbolAddress((void**)&WQK,  g_wqk);
    cudaGetSymbolAddress((void**)&WV,   g_wv);
    cudaGetSymbolAddress((void**)&W11,  g_w11);
    cudaGetSymbolAddress((void**)&W21,  g_w21);
    cudaGetSymbolAddress((void**)&WCAT, g_wcat);

    const int GSM = 3 * HSTG_BYTES;  // 110592
    cudaFuncSetAttribute(hgemm_k<4>, cudaFuncAttributeMaxDynamicSharedMemorySize, GSM);
    cudaFuncSetAttribute(hgemm_dual_k<1>, cudaFuncAttributeMaxDynamicSharedMemorySize, GSM);
    cudaFuncSetAttribute(hgemm_dual_k<3>, cudaFuncAttributeMaxDynamicSharedMemorySize, GSM);
    cudaFuncSetAttribute(tok_attn_mma_k, cudaFuncAttributeMaxDynamicSharedMemorySize, TOK_SMEM);
    cudaFuncSetAttribute(hid_attn_mma_k, cudaFuncAttributeMaxDynamicSharedMemorySize, HID_SMEM);

    // weight conversions + combined second-layer bias, one launch
    wcvt_k<<<4866, 256>>>(qk_w, v_w, f1w1, f2w1, f1w2, f2w2,
                          WQK, WV, W11, W21, WCAT, f1b2, f2b2, BC);
    l2norm_src_k<<<NTOK, 128>>>(src, S1h, SRCh);
    // projections: QK + V in one dual launch
    {
        Gp pqk = { S1h, WQK, qk_b, QKh, nullptr, nullptr, nullptr, 1024, 1024, 512, 8 };
        Gp pv  = { SRCh, WV, v_b, Vh, nullptr, nullptr, nullptr, 512, 512, 512, 4 };
        hgemm_dual_k<3><<<192 * 8 + 192 * 4, 256, GSM>>>(pqk, pv, 192 * 8);
    }
    // decay scan -> q1, k1 (half, head-major)
    decay_k<<<dim3(G, 2), 256>>>(QKh, alpha, Q1h, K1h);
    // attentions (fp16 mma, half I/O)
    tok_attn_mma_k<<<1024, 256, TOK_SMEM>>>(Q1h, K1h, Vh, OTr);
    hid_attn_mma_k<<<1024, 256, HID_SMEM>>>(QKh, Vh, OHr);
    // BN stats for both attention outputs, both finals, both weight folds
    bn_partial2_h_k<<<dim3(192, 2), 512>>>(OTr, OHr, PS, PQ, PS2, PQ2);
    bn_final2_k<<<128, 256>>>(PS, PQ, g_pre2, b_pre2, SC1, SH1,
                              PS2, PQ2, g_pre1, b_pre1, SC2, SH2);
    wfold2_k<<<512, 256>>>(W11, f1b1, W21, f2b1, SC1, SH1, SC2, SH2,
                           WF1, BF1, WF2, BF2);
    // FF first layers -> combined hidden [24576, 4096], one dual launch
    {
        Gp p1 = { OTr, WF1, BF1, HBh, nullptr, nullptr, nullptr, 2048, 4096, 512, 16 };
        Gp p2 = { OHr, WF2, BF2, HBh + 2048, nullptr, nullptr, nullptr, 2048, 4096, 512, 16 };
        hgemm_dual_k<1><<<192 * 32, 256, GSM>>>(p1, p2, 192 * 16);
    }
    // combined FF second layer: ACC = HB @ WCAT^T + BC + src, with fused BN partials
    {
        Gp pc = { HBh, WCAT, BC, ACC, src, PS, PQ, 512, 512, 4096, 4 };
        hgemm_k<4><<<192 * 4, 256, GSM>>>(pc);
    }
    // final BN(ACC) -> out (partials already produced by EPI-4 epilogue)
    bn_final_k<<<64, 256>>>(PS, PQ, g_attn, b_attn, SC1, SH1);
    bn_apply1_k<<<NELEM / 4 / 256, 256>>>(out, ACC, SC1, SH1);
}

// round 17
// speedup vs baseline: 1.0161x; 1.0161x over previous
#include <cuda_runtime.h>
#include <cuda_fp16.h>
#include <math.h>
#include <stdint.h>

#define G     128       // B*NV
#define HTOK  192
#define CH    512
#define NHD   8
#define HD    64
#define DFFC  2048
#define NTOK  24576     // G*HTOK
#define NELEM 12582912  // NTOK*CH

// ---------------- scratch (static device globals; allocation-free) ----------
__device__ float g_accb[NELEM];        // src + src2 (fp32)
__device__ float g_ps[192 * 512];
__device__ float g_pq[192 * 512];
__device__ float g_ps2[192 * 512];
__device__ float g_pq2[192 * 512];
__device__ float g_sc1[512];
__device__ float g_sh1[512];
__device__ float g_sc2[512];
__device__ float g_sh2[512];
__device__ float g_bf1[DFFC];          // folded bias FF1 (fp32)
__device__ float g_bf2[DFFC];          // folded bias FF2 (fp32)
__device__ float g_bc[512];            // combined second-layer bias
// fp16 buffers
__device__ __half g_qkh[NTOK * 1024];    // qk projection (half)
__device__ __half g_vh[NELEM];           // v projection (half)
__device__ __half g_q1h[NELEM];          // decayed q (half, head-major)
__device__ __half g_k1h[NELEM];          // decayed k
__device__ __half g_s1h[NELEM];          // normalized src
__device__ __half g_srch[NELEM];         // src
__device__ __half g_otr[NELEM];          // token-attn out (raw, half)
__device__ __half g_ohr[NELEM];          // hidden-attn out (raw, half)
__device__ __half g_hbh[NTOK * 4096];    // FF hidden (FF1 | FF2 columns)
__device__ __half g_wf1[DFFC * 512];     // folded W11
__device__ __half g_wf2[DFFC * 512];     // folded W21
__device__ __half g_wqk[1024 * 512];
__device__ __half g_wv[512 * 512];
__device__ __half g_w11[2048 * 512];
__device__ __half g_w21[2048 * 512];
__device__ __half g_wcat[512 * 4096];    // [W12 | W22] row-concat

__device__ __forceinline__ uint32_t smem_u32(const void* p) {
    uint32_t a;
    asm("{ .reg .u64 t; cvta.to.shared.u64 t, %1; cvt.u32.u64 %0, t; }"
        : "=r"(a) : "l"(p));
    return a;
}
__device__ __forceinline__ void mma_f16(float* c, const uint32_t* a, const uint32_t* b) {
    asm volatile(
        "mma.sync.aligned.m16n8k16.row.col.f32.f16.f16.f32 "
        "{%0,%1,%2,%3}, {%4,%5,%6,%7}, {%8,%9}, {%0,%1,%2,%3};"
        : "+f"(c[0]), "+f"(c[1]), "+f"(c[2]), "+f"(c[3])
        : "r"(a[0]), "r"(a[1]), "r"(a[2]), "r"(a[3]), "r"(b[0]), "r"(b[1]));
}
#define LDSM4(r, a)                                                            \
    asm volatile("ldmatrix.sync.aligned.m8n8.x4.shared.b16 {%0,%1,%2,%3}, [%4];" \
        : "=r"((r)[0]), "=r"((r)[1]), "=r"((r)[2]), "=r"((r)[3]) : "r"(a))
#define LDSM2(r, a)                                                            \
    asm volatile("ldmatrix.sync.aligned.m8n8.x2.shared.b16 {%0,%1}, [%2];"     \
        : "=r"((r)[0]), "=r"((r)[1]) : "r"(a))
#define LDSM4T(r, a)                                                           \
    asm volatile("ldmatrix.sync.aligned.m8n8.x4.trans.shared.b16 {%0,%1,%2,%3}, [%4];" \
        : "=r"((r)[0]), "=r"((r)[1]), "=r"((r)[2]), "=r"((r)[3]) : "r"(a))
#define LDSM2T(r, a)                                                           \
    asm volatile("ldmatrix.sync.aligned.m8n8.x2.trans.shared.b16 {%0,%1}, [%2];" \
        : "=r"((r)[0]), "=r"((r)[1]) : "r"(a))

// ============ fp16 mma GEMM, cp.async 3-stage: C = epi(A@B^T + bias) ========
// CTA tile 128x128, K-chunk 64, 8 warps (64x32), 2 CTAs/SM.
#define RSB 144                       // smem row stride bytes (64 halves + pad)
#define HSTG_BYTES (2 * 128 * RSB)    // 36864 per stage

struct Gp {
    const __half* A; const __half* B; const float* bias; void* C;
    const float* Xadd; float* ps; float* pq; int N; int ldc; int K; int gridN;
};

// EPI: 1 = GELU -> half, 3 = store half,
//      4 = fp32 store of acc+bias+Xadd, with fused per-chunk BN partial stats
template <int EPI>
__device__ __forceinline__ void gemm_body(const Gp p, int bid, char* hsm) {
    const int tid = threadIdx.x;
    const int wid = tid >> 5, lane = tid & 31;
    const int wm = wid >> 2, wn = wid & 3;
    const int g = lane >> 2, tig = lane & 3;

    int per = 8 * p.gridN;
    int grp = bid / per, rem = bid - grp * per;
    const int bm = (grp * 8 + (rem & 7)) * 128;
    const int bn = (rem >> 3) * 128;

    const __half* __restrict__ A = p.A;
    const __half* __restrict__ B = p.B;
    const int K = p.K;
    const uint32_t sbase = smem_u32(hsm);
    const int CCH = K >> 6;

    const int c_row = tid >> 3;
    const int c_cq = tid & 7;
    #define CPYH(c, s) do {                                                     \
        int _kc = (c) << 6;                                                     \
        uint32_t _sa = sbase + (uint32_t)(s) * HSTG_BYTES;                      \
        _Pragma("unroll")                                                       \
        for (int _i = 0; _i < 4; _i++) {                                        \
            int _row = c_row + _i * 32;                                         \
            uint32_t _off = (uint32_t)_row * RSB + (uint32_t)c_cq * 16u;        \
            const __half* _ga = A + (size_t)(bm + _row) * K + _kc + c_cq * 8;   \
            asm volatile("cp.async.cg.shared.global [%0], [%1], 16;"            \
                         :: "r"(_sa + _off), "l"(_ga));                         \
            const __half* _gb = B + (size_t)(bn + _row) * K + _kc + c_cq * 8;   \
            asm volatile("cp.async.cg.shared.global [%0], [%1], 16;"            \
                         :: "r"(_sa + 18432u + _off), "l"(_gb));                \
        }                                                                       \
    } while (0)

    CPYH(0, 0);
    asm volatile("cp.async.commit_group;" ::: "memory");
    CPYH(1, 1);
    asm volatile("cp.async.commit_group;" ::: "memory");

    float acc[4][4][4];
    #pragma unroll
    for (int mt = 0; mt < 4; mt++)
        #pragma unroll
        for (int nt = 0; nt < 4; nt++)
            #pragma unroll
            for (int i = 0; i < 4; i++) acc[mt][nt][i] = 0.f;

    asm volatile("cp.async.wait_group 1;" ::: "memory");
    __syncthreads();

    const int lr = lane & 7, sel = lane >> 3;
    const uint32_t aoff =
        (uint32_t)(wm * 64 + (sel & 1) * 8 + lr) * RSB + (uint32_t)((sel >> 1) * 8) * 2;
    const uint32_t boff =
        (uint32_t)(wn * 32 + lr) * RSB + (uint32_t)((sel & 1) * 8) * 2;

    for (int c = 0; c < CCH; c++) {
        int rs = c % 3;
        if (c + 2 < CCH) {
            int ws = rs + 2; if (ws >= 3) ws -= 3;
            CPYH(c + 2, ws);
        }
        asm volatile("cp.async.commit_group;" ::: "memory");

        uint32_t sA = sbase + (uint32_t)rs * HSTG_BYTES;
        uint32_t sB = sA + 18432u;
        #pragma unroll
        for (int kt = 0; kt < 4; kt++) {
            uint32_t af[4][4], bf[4][2];
            #pragma unroll
            for (int mt = 0; mt < 4; mt++)
                LDSM4(af[mt], sA + aoff + (uint32_t)(mt * 16) * RSB + (uint32_t)kt * 32u);
            #pragma unroll
            for (int nt = 0; nt < 4; nt++)
                LDSM2(bf[nt], sB + boff + (uint32_t)(nt * 8) * RSB + (uint32_t)kt * 32u);
            #pragma unroll
            for (int mt = 0; mt < 4; mt++)
                #pragma unroll
                for (int nt = 0; nt < 4; nt++)
                    mma_f16(acc[mt][nt], af[mt], bf[nt]);
        }
        asm volatile("cp.async.wait_group 1;" ::: "memory");
        __syncthreads();
    }
    #undef CPYH

    const int ldc = p.ldc;
    if (EPI == 1 || EPI == 3) {
        #pragma unroll
        for (int mt = 0; mt < 4; mt++) {
            int m0 = bm + wm * 64 + mt * 16 + g;
            #pragma unroll
            for (int nt = 0; nt < 4; nt++) {
                int n0 = bn + wn * 32 + nt * 8 + tig * 2;
                float b0 = p.bias[n0], b1 = p.bias[n0 + 1];
                float v00 = acc[mt][nt][0] + b0;
                float v01 = acc[mt][nt][1] + b1;
                float v10 = acc[mt][nt][2] + b0;
                float v11 = acc[mt][nt][3] + b1;
                if (EPI == 1) {
                    v00 = 0.5f * v00 * (1.0f + erff(v00 * 0.70710678118654752f));
                    v01 = 0.5f * v01 * (1.0f + erff(v01 * 0.70710678118654752f));
                    v10 = 0.5f * v10 * (1.0f + erff(v10 * 0.70710678118654752f));
                    v11 = 0.5f * v11 * (1.0f + erff(v11 * 0.70710678118654752f));
                }
                __half* Ch = (__half*)p.C;
                *reinterpret_cast<__half2*>(Ch + (size_t)m0 * ldc + n0) =
                    __floats2half2_rn(v00, v01);
                *reinterpret_cast<__half2*>(Ch + (size_t)(m0 + 8) * ldc + n0) =
                    __floats2half2_rn(v10, v11);
            }
        }
    } else {  // EPI == 4: fp32 store of acc + bias + Xadd, fused BN partials
        float* ssum = reinterpret_cast<float*>(hsm);      // [16][130]
        float* ssq = ssum + 16 * 130;                     // [16][130]
        #pragma unroll
        for (int nt = 0; nt < 4; nt++) {
            int n0 = bn + wn * 32 + nt * 8 + tig * 2;
            float b0 = p.bias[n0], b1 = p.bias[n0 + 1];
            float cs0 = 0.f, cs1 = 0.f, cq0 = 0.f, cq1 = 0.f;
            #pragma unroll
            for (int mt = 0; mt < 4; mt++) {
                int m0 = bm + wm * 64 + mt * 16 + g;
                float v00 = acc[mt][nt][0] + b0;
                float v01 = acc[mt][nt][1] + b1;
                float v10 = acc[mt][nt][2] + b0;
                float v11 = acc[mt][nt][3] + b1;
                float2 s0 = *reinterpret_cast<const float2*>(p.Xadd + (size_t)m0 * ldc + n0);
                float2 s1 = *reinterpret_cast<const float2*>(p.Xadd + (size_t)(m0 + 8) * ldc + n0);
                v00 += s0.x; v01 += s0.y;
                v10 += s1.x; v11 += s1.y;
                *reinterpret_cast<float2*>((float*)p.C + (size_t)m0 * ldc + n0) =
                    make_float2(v00, v01);
                *reinterpret_cast<float2*>((float*)p.C + (size_t)(m0 + 8) * ldc + n0) =
                    make_float2(v10, v11);
                cs0 += v00 + v10; cs1 += v01 + v11;
                cq0 += v00 * v00 + v10 * v10;
                cq1 += v01 * v01 + v11 * v11;
            }
            int contrib = wm * 8 + g;               // 0..15
            int lc = wn * 32 + nt * 8 + tig * 2;    // local col 0..127
            *reinterpret_cast<float2*>(ssum + contrib * 130 + lc) = make_float2(cs0, cs1);
            *reinterpret_cast<float2*>(ssq + contrib * 130 + lc) = make_float2(cq0, cq1);
        }
        __syncthreads();
        if (tid < 128) {
            float s = 0.f, q = 0.f;
            #pragma unroll
            for (int k = 0; k < 16; k++) {
                s += ssum[k * 130 + tid];
                q += ssq[k * 130 + tid];
            }
            int idx = (bm >> 7) * 512 + bn + tid;
            p.ps[idx] = s;
            p.pq[idx] = q;
        }
    }
}

template <int EPI>
__global__ void __launch_bounds__(256, 2) hgemm_k(Gp p) {
    extern __shared__ char hsm[];
    gemm_body<EPI>(p, blockIdx.x, hsm);
}

template <int EPI>
__global__ void __launch_bounds__(256, 2) hgemm_dual_k(Gp p0, Gp p1, int split) {
    extern __shared__ char hsm[];
    if ((int)blockIdx.x < split) gemm_body<EPI>(p0, blockIdx.x, hsm);
    else                         gemm_body<EPI>(p1, blockIdx.x - split, hsm);
}

// -------- fused weight convert + combined bias: last block does bias add ----
__global__ void wcvt_k(const float* __restrict__ qkw, const float* __restrict__ vw,
                       const float* __restrict__ w11, const float* __restrict__ w21,
                       const float* __restrict__ w12, const float* __restrict__ w22,
                       __half* __restrict__ dqk, __half* __restrict__ dv,
                       __half* __restrict__ d11, __half* __restrict__ d21,
                       __half* __restrict__ dcat,
                       const float* __restrict__ b12, const float* __restrict__ b22,
                       float* __restrict__ bc) {
    if (blockIdx.x >= 4864) {
        int j = (blockIdx.x - 4864) * 256 + threadIdx.x;
        if (j < 512) bc[j] = b12[j] + b22[j];
        return;
    }
    int i = blockIdx.x * blockDim.x + threadIdx.x;  // float4 index, < 1245184
    const float* s; __half* d; int sof, dof;
    if (i < 131072)       { s = qkw; d = dqk; sof = i; dof = sof; }
    else if (i < 196608)  { s = vw;  d = dv;  sof = i - 131072; dof = sof; }
    else if (i < 458752)  { s = w11; d = d11; sof = i - 196608; dof = sof; }
    else if (i < 720896)  { s = w21; d = d21; sof = i - 458752; dof = sof; }
    else if (i < 983040)  { s = w12; d = dcat; sof = i - 720896;
                            dof = (sof >> 9) * 1024 + (sof & 511); }
    else                  { s = w22; d = dcat; sof = i - 983040;
                            dof = (sof >> 9) * 1024 + 512 + (sof & 511); }
    float4 v = reinterpret_cast<const float4*>(s)[sof];
    __half2* yp = reinterpret_cast<__half2*>(d + (size_t)dof * 4);
    yp[0] = __floats2half2_rn(v.x, v.y);
    yp[1] = __floats2half2_rn(v.z, v.w);
}

// ------- fold BN into FF first-layer weight: Wo = W*sc, biaso = b + W@sh ----
__global__ void wfold2_k(const __half* __restrict__ W11, const float* __restrict__ b11,
                         const __half* __restrict__ W21, const float* __restrict__ b21,
                         const float* __restrict__ sc1, const float* __restrict__ sh1,
                         const float* __restrict__ sc2, const float* __restrict__ sh2,
                         __half* __restrict__ Wo1, float* __restrict__ bo1,
                         __half* __restrict__ Wo2, float* __restrict__ bo2) {
    int blk = blockIdx.x;
    const __half* W; const float* bias; const float* sc; const float* sh;
    __half* Wo; float* bo;
    int row = (blk & 255) * 8 + (threadIdx.x >> 5);
    if (blk < 256) { W = W11; bias = b11; sc = sc1; sh = sh1; Wo = Wo1; bo = bo1; }
    else           { W = W21; bias = b21; sc = sc2; sh = sh2; Wo = Wo2; bo = bo2; }
    int lane = threadIdx.x & 31;
    const __half2* wr = reinterpret_cast<const __half2*>(W + (size_t)row * 512);
    __half2* wo = reinterpret_cast<__half2*>(Wo + (size_t)row * 512);
    float dot = 0.f;
    #pragma unroll
    for (int k = 0; k < 8; k++) {
        int j = lane + k * 32;
        float2 wf = __half22float2(wr[j]);
        dot += sh[2 * j] * wf.x + sh[2 * j + 1] * wf.y;
        wo[j] = __floats2half2_rn(wf.x * sc[2 * j], wf.y * sc[2 * j + 1]);
    }
    #pragma unroll
    for (int o = 16; o > 0; o >>= 1) dot += __shfl_xor_sync(0xffffffffu, dot, o);
    if (lane == 0) bo[row] = bias[row] + dot;
}

// ------------- fused: src -> srch (half) + l2-normalized src (half) ---------
__global__ void l2norm_src_k(const float* __restrict__ X,
                             __half* __restrict__ Yn, __half* __restrict__ Yr) {
    __shared__ float red[4];
    int row = blockIdx.x;
    int tid = threadIdx.x;  // 128
    const float4* xp = reinterpret_cast<const float4*>(X + (size_t)row * CH);
    float4 v = xp[tid];
    float ss = v.x * v.x + v.y * v.y + v.z * v.z + v.w * v.w;
    #pragma unroll
    for (int o = 16; o > 0; o >>= 1) ss += __shfl_xor_sync(0xffffffffu, ss, o);
    if ((tid & 31) == 0) red[tid >> 5] = ss;
    __syncthreads();
    float rn = rsqrtf(red[0] + red[1] + red[2] + red[3]);
    __half2* yr = reinterpret_cast<__half2*>(Yr + (size_t)row * CH + tid * 4);
    yr[0] = __floats2half2_rn(v.x, v.y);
    yr[1] = __floats2half2_rn(v.z, v.w);
    __half2* yn = reinterpret_cast<__half2*>(Yn + (size_t)row * CH + tid * 4);
    yn[0] = __floats2half2_rn(v.x * rn, v.y * rn);
    yn[1] = __floats2half2_rn(v.z * rn, v.w * rn);
}

// ---------- exponential-decay scan: one thread per channel (512/block) ------
__global__ void __launch_bounds__(512) decay_k(
    const __half* __restrict__ QK, const float* __restrict__ alpha,
    __half* __restrict__ Q1, __half* __restrict__ K1) {
    int g = blockIdx.x;      // 0..127
    int which = blockIdx.y;  // 0=q, 1=k
    int ch = threadIdx.x;    // 0..511
    int d = ch & 63;
    int nh = ch >> 6;
    float a = 1.f / (1.f + expf(-alpha[d]));
    float l2r = log2f(1.f - a);
    const __half* x = QK + (size_t)g * (HTOK * 1024) + which * 512 + ch;
    __half* y = (which ? K1 : Q1) + (size_t)g * (NHD * HTOK * HD) +
                (size_t)nh * (HTOK * HD) + d;
    float z = 0.f;
    for (int t = 0; t < HTOK; ++t) {
        z = fmaf(__half2float(x[(size_t)t * 1024]), exp2f((float)t * l2r), z);
        y[(size_t)t * 64] = __float2half_rn(a * exp2f((float)(HTOK - 1 - t) * l2r) * z);
    }
}

// ============ token attention, fp16 mma: per-head 192x192x64 ================
#define SRF 196    // Sf float stride (784B rows)
#define TOK_SMEM 206592

__global__ void __launch_bounds__(256, 1) tok_attn_mma_k(
    const __half* __restrict__ Q1, const __half* __restrict__ K1,
    const __half* __restrict__ V, __half* __restrict__ O) {
    extern __shared__ char smc[];
    const uint32_t sb = smem_u32(smc);
    const uint32_t sQ = sb, sK = sb + 27648u, sS = sb + 55296u;
    float* Sf = reinterpret_cast<float*>(smc + 55296);
    float* linv = reinterpret_cast<float*>(smc + 205824);
    const int head = blockIdx.x;
    const int g = head >> 3, nh = head & 7;
    const int tid = threadIdx.x, wid = tid >> 5, lane = tid & 31;
    const int wm = wid >> 1, wn = wid & 1;        // 4m x 2n
    const int gq = lane >> 2, tg = lane & 3;
    const int lr = lane & 7, sel = lane >> 3;

    {
        const __half* Qg = Q1 + (size_t)head * 12288;
        const __half* Kg = K1 + (size_t)head * 12288;
        #pragma unroll
        for (int i = 0; i < 6; i++) {
            int idx = i * 256 + tid;
            int row = idx >> 3, cq = idx & 7;
            uint32_t off = (uint32_t)row * RSB + (uint32_t)cq * 16u;
            asm volatile("cp.async.cg.shared.global [%0], [%1], 16;"
                         :: "r"(sQ + off), "l"(Qg + row * 64 + cq * 8));
            asm volatile("cp.async.cg.shared.global [%0], [%1], 16;"
                         :: "r"(sK + off), "l"(Kg + row * 64 + cq * 8));
        }
        asm volatile("cp.async.commit_group;" ::: "memory");
        asm volatile("cp.async.wait_group 0;" ::: "memory");
    }
    __syncthreads();

    // S = Q1 @ K1^T : warp tile 48x96
    {
        float acc[3][12][4];
        #pragma unroll
        for (int mt = 0; mt < 3; mt++)
            #pragma unroll
            for (int nt = 0; nt < 12; nt++)
                #pragma unroll
                for (int i = 0; i < 4; i++) acc[mt][nt][i] = 0.f;
        const int m0w = wm * 48, n0w = wn * 96;
        #pragma unroll
        for (int kt = 0; kt < 4; kt++) {
            uint32_t af[3][4], bf[12][2];
            #pragma unroll
            for (int mt = 0; mt < 3; mt++)
                LDSM4(af[mt], sQ + (uint32_t)(m0w + mt * 16 + (sel & 1) * 8 + lr) * RSB +
                              (uint32_t)(kt * 16 + (sel >> 1) * 8) * 2u);
            #pragma unroll
            for (int nt = 0; nt < 12; nt++)
                LDSM2(bf[nt], sK + (uint32_t)(n0w + nt * 8 + lr) * RSB +
                              (uint32_t)(kt * 16 + (sel & 1) * 8) * 2u);
            #pragma unroll
            for (int mt = 0; mt < 3; mt++)
                #pragma unroll
                for (int nt = 0; nt < 12; nt++)
                    mma_f16(acc[mt][nt], af[mt], bf[nt]);
        }
        #pragma unroll
        for (int mt = 0; mt < 3; mt++) {
            int r0 = m0w + mt * 16 + gq;
            #pragma unroll
            for (int nt = 0; nt < 12; nt++) {
                int c0 = n0w + nt * 8 + tg * 2;
                Sf[r0 * SRF + c0]           = acc[mt][nt][0] * 8.0f;
                Sf[r0 * SRF + c0 + 1]       = acc[mt][nt][1] * 8.0f;
                Sf[(r0 + 8) * SRF + c0]     = acc[mt][nt][2] * 8.0f;
                Sf[(r0 + 8) * SRF + c0 + 1] = acc[mt][nt][3] * 8.0f;
            }
        }
    }
    __syncthreads();

    // V load (half, direct cp.async) into Q1 region; overlaps with softmax
    {
        const __half* Vg = V + (size_t)(g * 192) * 512 + nh * 64;
        #pragma unroll
        for (int i = 0; i < 6; i++) {
            int idx = i * 256 + tid;
            int row = idx >> 3, cq = idx & 7;
            asm volatile("cp.async.cg.shared.global [%0], [%1], 16;"
                         :: "r"(sQ + (uint32_t)row * RSB + (uint32_t)cq * 16u),
                            "l"(Vg + (size_t)row * 512 + cq * 8));
        }
        asm volatile("cp.async.commit_group;" ::: "memory");
    }
    // softmax over rows (tid < 192)
    if (tid < 192) {
        float* row = Sf + tid * SRF;
        float mx = -1e30f;
        #pragma unroll 8
        for (int j = 0; j < 192; j += 4) {
            float4 v = *reinterpret_cast<const float4*>(row + j);
            mx = fmaxf(mx, fmaxf(fmaxf(v.x, v.y), fmaxf(v.z, v.w)));
        }
        float sum = 0.f;
        __half2* ph = reinterpret_cast<__half2*>(row);
        #pragma unroll 8
        for (int j = 0; j < 192; j += 4) {
            float4 v = *reinterpret_cast<const float4*>(row + j);
            float e0 = __expf(v.x - mx), e1 = __expf(v.y - mx);
            float e2 = __expf(v.z - mx), e3 = __expf(v.w - mx);
            sum += (e0 + e1) + (e2 + e3);
            ph[j >> 1] = __floats2half2_rn(e0, e1);
            ph[(j >> 1) + 1] = __floats2half2_rn(e2, e3);
        }
        linv[tid] = 1.0f / sum;
    }
    asm volatile("cp.async.wait_group 0;" ::: "memory");
    __syncthreads();

    // O = P @ V : warp tile 48x32 over k=192
    {
        float acc[3][4][4];
        #pragma unroll
        for (int mt = 0; mt < 3; mt++)
            #pragma unroll
            for (int nt = 0; nt < 4; nt++)
                #pragma unroll
                for (int i = 0; i < 4; i++) acc[mt][nt][i] = 0.f;
        const int m0 = wm * 48, n0 = wn * 32;
        #pragma unroll
        for (int kt = 0; kt < 12; kt++) {
            uint32_t af[3][4], bf[4][2];
            #pragma unroll
            for (int mt = 0; mt < 3; mt++)
                LDSM4(af[mt], sS + (uint32_t)(m0 + mt * 16 + (sel & 1) * 8 + lr) * 784u +
                              (uint32_t)(kt * 16 + (sel >> 1) * 8) * 2u);
            #pragma unroll
            for (int nt = 0; nt < 4; nt++)
                LDSM2T(bf[nt], sQ + (uint32_t)(kt * 16 + (sel & 1) * 8 + lr) * RSB +
                               (uint32_t)(n0 + nt * 8) * 2u);
            #pragma unroll
            for (int mt = 0; mt < 3; mt++)
                #pragma unroll
                for (int nt = 0; nt < 4; nt++)
                    mma_f16(acc[mt][nt], af[mt], bf[nt]);
        }
        __half* Og = O + (size_t)head * 12288;
        #pragma unroll
        for (int mt = 0; mt < 3; mt++) {
            int r = m0 + mt * 16 + gq;
            float i0 = linv[r], i1 = linv[r + 8];
            #pragma unroll
            for (int nt = 0; nt < 4; nt++) {
                int c = n0 + nt * 8 + tg * 2;
                *reinterpret_cast<__half2*>(Og + r * 64 + c) =
                    __floats2half2_rn(acc[mt][nt][0] * i0, acc[mt][nt][1] * i0);
                *reinterpret_cast<__half2*>(Og + (r + 8) * 64 + c) =
                    __floats2half2_rn(acc[mt][nt][2] * i1, acc[mt][nt][3] * i1);
            }
        }
    }
}

// ============ hidden attention, fp16 mma: per-head 64x64 over 192 ===========
#define HID_SMEM 109824

__global__ void __launch_bounds__(256, 2) hid_attn_mma_k(
    const __half* __restrict__ QK, const __half* __restrict__ V,
    __half* __restrict__ O) {
    extern __shared__ char smc[];
    const uint32_t sb = smem_u32(smc);
    const uint32_t sQ = sb, sK = sb + 27648u, sV = sb + 55296u, sP = sb + 100352u;
    float* S2f = reinterpret_cast<float*>(smc + 82944);
    float* linv2 = reinterpret_cast<float*>(smc + 109568);
    const int head = blockIdx.x;
    const int g = head >> 3, nh = head & 7;
    const int tid = threadIdx.x, wid = tid >> 5, lane = tid & 31;
    const int gq = lane >> 2, tg = lane & 3;
    const int lr = lane & 7, sel = lane >> 3;

    {
        const __half* Qg = QK + (size_t)(g * 192) * 1024 + nh * 64;
        const __half* Kg = Qg + 512;
        const __half* Vg = V + (size_t)(g * 192) * 512 + nh * 64;
        #pragma unroll
        for (int i = 0; i < 6; i++) {
            int idx = i * 256 + tid;
            int row = idx >> 3, cq = idx & 7;
            uint32_t off = (uint32_t)row * RSB + (uint32_t)cq * 16u;
            asm volatile("cp.async.cg.shared.global [%0], [%1], 16;"
                         :: "r"(sQ + off), "l"(Qg + (size_t)row * 1024 + cq * 8));
            asm volatile("cp.async.cg.shared.global [%0], [%1], 16;"
                         :: "r"(sK + off), "l"(Kg + (size_t)row * 1024 + cq * 8));
            asm volatile("cp.async.cg.shared.global [%0], [%1], 16;"
                         :: "r"(sV + off), "l"(Vg + (size_t)row * 512 + cq * 8));
        }
        asm volatile("cp.async.commit_group;" ::: "memory");
        asm volatile("cp.async.wait_group 0;" ::: "memory");
    }
    __syncthreads();

    // S2 = Q^T @ K (64x64 over a=192)
    {
        float acc[2][2][4];
        #pragma unroll
        for (int mt = 0; mt < 2; mt++)
            #pragma unroll
            for (int nt = 0; nt < 2; nt++)
                #pragma unroll
                for (int i = 0; i < 4; i++) acc[mt][nt][i] = 0.f;
        const int m0 = (wid >> 2) * 32, n0 = (wid & 3) * 16;
        #pragma unroll
        for (int kt = 0; kt < 12; kt++) {
            uint32_t af[2][4], bf[2][2];
            #pragma unroll
            for (int mt = 0; mt < 2; mt++)
                LDSM4T(af[mt], sQ + (uint32_t)(kt * 16 + (sel >> 1) * 8 + lr) * RSB +
                               (uint32_t)(m0 + mt * 16 + (sel & 1) * 8) * 2u);
            #pragma unroll
            for (int nt = 0; nt < 2; nt++)
                LDSM2T(bf[nt], sK + (uint32_t)(kt * 16 + (sel & 1) * 8 + lr) * RSB +
                               (uint32_t)(n0 + nt * 8) * 2u);
            #pragma unroll
            for (int mt = 0; mt < 2; mt++)
                #pragma unroll
                for (int nt = 0; nt < 2; nt++)
                    mma_f16(acc[mt][nt], af[mt], bf[nt]);
        }
        #pragma unroll
        for (int mt = 0; mt < 2; mt++) {
            int r0 = m0 + mt * 16 + gq;
            #pragma unroll
            for (int nt = 0; nt < 2; nt++) {
                int c0 = n0 + nt * 8 + tg * 2;
                S2f[r0 * 68 + c0]           = acc[mt][nt][0] * 13.856406460551018f;
                S2f[r0 * 68 + c0 + 1]       = acc[mt][nt][1] * 13.856406460551018f;
                S2f[(r0 + 8) * 68 + c0]     = acc[mt][nt][2] * 13.856406460551018f;
                S2f[(r0 + 8) * 68 + c0 + 1] = acc[mt][nt][3] * 13.856406460551018f;
            }
        }
    }
    __syncthreads();

    if (tid < 64) {
        float* row = S2f + tid * 68;
        float mx = -1e30f;
        #pragma unroll
        for (int j = 0; j < 64; j += 4) {
            float4 v = *reinterpret_cast<const float4*>(row + j);
            mx = fmaxf(mx, fmaxf(fmaxf(v.x, v.y), fmaxf(v.z, v.w)));
        }
        float sum = 0.f;
        __half2* ph = reinterpret_cast<__half2*>(smc + 100352 + tid * RSB);
        #pragma unroll
        for (int j = 0; j < 64; j += 4) {
            float4 v = *reinterpret_cast<const float4*>(row + j);
            float e0 = __expf(v.x - mx), e1 = __expf(v.y - mx);
            float e2 = __expf(v.z - mx), e3 = __expf(v.w - mx);
            sum += (e0 + e1) + (e2 + e3);
            ph[j >> 1] = __floats2half2_rn(e0, e1);
            ph[(j >> 1) + 1] = __floats2half2_rn(e2, e3);
        }
        linv2[tid] = 1.0f / sum;
    }
    __syncthreads();

    // O2 = V @ P2^T (192x64 over f=64)
    {
        float acc[3][4][4];
        #pragma unroll
        for (int mt = 0; mt < 3; mt++)
            #pragma unroll
            for (int nt = 0; nt < 4; nt++)
                #pragma unroll
                for (int i = 0; i < 4; i++) acc[mt][nt][i] = 0.f;
        const int m0 = (wid >> 1) * 48, n0 = (wid & 1) * 32;
        #pragma unroll
        for (int kt = 0; kt < 4; kt++) {
            uint32_t af[3][4], bf[4][2];
            #pragma unroll
            for (int mt = 0; mt < 3; mt++)
                LDSM4(af[mt], sV + (uint32_t)(m0 + mt * 16 + (sel & 1) * 8 + lr) * RSB +
                              (uint32_t)(kt * 16 + (sel >> 1) * 8) * 2u);
            #pragma unroll
            for (int nt = 0; nt < 4; nt++)
                LDSM2(bf[nt], sP + (uint32_t)(n0 + nt * 8 + lr) * RSB +
                              (uint32_t)(kt * 16 + (sel & 1) * 8) * 2u);
            #pragma unroll
            for (int mt = 0; mt < 3; mt++)
                #pragma unroll
                for (int nt = 0; nt < 4; nt++)
                    mma_f16(acc[mt][nt], af[mt], bf[nt]);
        }
        __half* Og = O + (size_t)head * 12288;
        #pragma unroll
        for (int mt = 0; mt < 3; mt++) {
            int r = m0 + mt * 16 + gq;
            #pragma unroll
            for (int nt = 0; nt < 4; nt++) {
                int c = n0 + nt * 8 + tg * 2;
                float i0 = linv2[c], i1 = linv2[c + 1];
                *reinterpret_cast<__half2*>(Og + r * 64 + c) =
                    __floats2half2_rn(acc[mt][nt][0] * i0, acc[mt][nt][1] * i1);
                *reinterpret_cast<__half2*>(Og + (r + 8) * 64 + c) =
                    __floats2half2_rn(acc[mt][nt][2] * i0, acc[mt][nt][3] * i1);
            }
        }
    }
}

// ---------------- BatchNorm (train-mode batch stats) ------------------------
__global__ void bn_partial2_h_k(const __half* __restrict__ X1, const __half* __restrict__ X2,
                                float* __restrict__ ps, float* __restrict__ pq,
                                float* __restrict__ ps2, float* __restrict__ pq2) {
    int chunk = blockIdx.x;
    int ch = threadIdx.x;
    const __half* X = blockIdx.y ? X2 : X1;
    float* psum = blockIdx.y ? ps2 : ps;
    float* psq = blockIdx.y ? pq2 : pq;
    const __half* p = X + (size_t)chunk * 128 * CH + ch;
    float s = 0.f, q = 0.f;
    for (int r = 0; r < 128; r++) {
        float v = __half2float(p[(size_t)r * CH]);
        s += v; q = fmaf(v, v, q);
    }
    psum[chunk * CH + ch] = s;
    psq[chunk * CH + ch] = q;
}

__device__ __forceinline__ void bn_final_body(
    const float* psum, const float* psq, const float* gamma, const float* beta,
    float* scale, float* shift, int ch, int lane) {
    float s = 0.f, q = 0.f;
    for (int c = lane; c < 192; c += 32) {
        s += psum[c * CH + ch];
        q += psq[c * CH + ch];
    }
    #pragma unroll
    for (int o = 16; o > 0; o >>= 1) {
        s += __shfl_xor_sync(0xffffffffu, s, o);
        q += __shfl_xor_sync(0xffffffffu, q, o);
    }
    if (lane == 0) {
        float mu = s * (1.0f / NTOK);
        float var = q * (1.0f / NTOK) - mu * mu;
        float sc = gamma[ch] * rsqrtf(var + 1e-5f);
        scale[ch] = sc;
        shift[ch] = beta[ch] - mu * sc;
    }
}

__global__ void bn_final_k(const float* __restrict__ psum, const float* __restrict__ psq,
                           const float* __restrict__ gamma, const float* __restrict__ beta,
                           float* __restrict__ scale, float* __restrict__ shift) {
    int ch = blockIdx.x * 8 + (threadIdx.x >> 5);
    bn_final_body(psum, psq, gamma, beta, scale, shift, ch, threadIdx.x & 31);
}

__global__ void bn_final2_k(const float* __restrict__ ps, const float* __restrict__ pq,
                            const float* __restrict__ g1, const float* __restrict__ b1,
                            float* __restrict__ sc1v, float* __restrict__ sh1v,
                            const float* __restrict__ ps2, const float* __restrict__ pq2,
                            const float* __restrict__ g2, const float* __restrict__ b2,
                            float* __restrict__ sc2v, float* __restrict__ sh2v) {
    int blk = blockIdx.x;
    int ch = (blk & 63) * 8 + (threadIdx.x >> 5);
    int lane = threadIdx.x & 31;
    if (blk < 64) bn_final_body(ps, pq, g1, b1, sc1v, sh1v, ch, lane);
    else          bn_final_body(ps2, pq2, g2, b2, sc2v, sh2v, ch, lane);
}

__global__ void bn_apply1_k(float* __restrict__ Y, const float* __restrict__ X,
                            const float* __restrict__ scale, const float* __restrict__ shift) {
    int i = blockIdx.x * blockDim.x + threadIdx.x;
    int ch4 = (i & 127) << 2;
    float4 x = reinterpret_cast<const float4*>(X)[i];
    x.x = fmaf(x.x, scale[ch4 + 0], shift[ch4 + 0]);
    x.y = fmaf(x.y, scale[ch4 + 1], shift[ch4 + 1]);
    x.z = fmaf(x.z, scale[ch4 + 2], shift[ch4 + 2]);
    x.w = fmaf(x.w, scale[ch4 + 3], shift[ch4 + 3]);
    reinterpret_cast<float4*>(Y)[i] = x;
}

// ---------------- driver ----------------------------------------------------
extern "C" void kernel_launch(void* const* d_in, const int* in_sizes, int n_in,
                              void* d_out, int out_size) {
    const float* src    = (const float*)d_in[0];
    const float* qk_w   = (const float*)d_in[1];
    const float* qk_b   = (const float*)d_in[2];
    const float* v_w    = (const float*)d_in[3];
    const float* v_b    = (const float*)d_in[4];
    const float* alpha  = (const float*)d_in[5];
    const float* g_pre1 = (const float*)d_in[6];
    const float* b_pre1 = (const float*)d_in[7];
    const float* g_pre2 = (const float*)d_in[8];
    const float* b_pre2 = (const float*)d_in[9];
    const float* f1w1   = (const float*)d_in[10];
    const float* f1b1   = (const float*)d_in[11];
    const float* f1w2   = (const float*)d_in[12];
    const float* f1b2   = (const float*)d_in[13];
    const float* f2w1   = (const float*)d_in[14];
    const float* f2b1   = (const float*)d_in[15];
    const float* f2w2   = (const float*)d_in[16];
    const float* f2b2   = (const float*)d_in[17];
    const float* g_attn = (const float*)d_in[18];
    const float* b_attn = (const float*)d_in[19];
    float* out = (float*)d_out;

    float *ACC, *PS, *PQ, *PS2, *PQ2, *SC1, *SH1, *SC2, *SH2, *BF1, *BF2, *BC;
    __half *QKh, *Vh, *Q1h, *K1h, *S1h, *SRCh, *OTr, *OHr, *HBh, *WF1, *WF2;
    __half *WQK, *WV, *W11, *W21, *WCAT;
    cudaGetSymbolAddress((void**)&ACC, g_accb);
    cudaGetSymbolAddress((void**)&PS,  g_ps);
    cudaGetSymbolAddress((void**)&PQ,  g_pq);
    cudaGetSymbolAddress((void**)&PS2, g_ps2);
    cudaGetSymbolAddress((void**)&PQ2, g_pq2);
    cudaGetSymbolAddress((void**)&SC1, g_sc1);
    cudaGetSymbolAddress((void**)&SH1, g_sh1);
    cudaGetSymbolAddress((void**)&SC2, g_sc2);
    cudaGetSymbolAddress((void**)&SH2, g_sh2);
    cudaGetSymbolAddress((void**)&BF1, g_bf1);
    cudaGetSymbolAddress((void**)&BF2, g_bf2);
    cudaGetSymbolAddress((void**)&BC,  g_bc);
    cudaGetSymbolAddress((void**)&QKh,  g_qkh);
    cudaGetSymbolAddress((void**)&Vh,   g_vh);
    cudaGetSymbolAddress((void**)&Q1h,  g_q1h);
    cudaGetSymbolAddress((void**)&K1h,  g_k1h);
    cudaGetSymbolAddress((void**)&S1h,  g_s1h);
    cudaGetSymbolAddress((void**)&SRCh, g_srch);
    cudaGetSymbolAddress((void**)&OTr,  g_otr);
    cudaGetSymbolAddress((void**)&OHr,  g_ohr);
    cudaGetSymbolAddress((void**)&HBh,  g_hbh);
    cudaGetSymbolAddress((void**)&WF1,  g_wf1);
    cudaGetSymbolAddress((void**)&WF2,  g_wf2);
    cudaGetSymbolAddress((void**)&WQK,  g_wqk);
    cudaGetSymbolAddress((void**)&WV,   g_wv);
    cudaGetSymbolAddress((void**)&W11,  g_w11);
    cudaGetSymbolAddress((void**)&W21,  g_w21);
    cudaGetSymbolAddress((void**)&WCAT, g_wcat);

    const int GSM = 3 * HSTG_BYTES;  // 110592
    cudaFuncSetAttribute(hgemm_k<4>, cudaFuncAttributeMaxDynamicSharedMemorySize, GSM);
    cudaFuncSetAttribute(hgemm_dual_k<1>, cudaFuncAttributeMaxDynamicSharedMemorySize, GSM);
    cudaFuncSetAttribute(hgemm_dual_k<3>, cudaFuncAttributeMaxDynamicSharedMemorySize, GSM);
    cudaFuncSetAttribute(tok_attn_mma_k, cudaFuncAttributeMaxDynamicSharedMemorySize, TOK_SMEM);
    cudaFuncSetAttribute(hid_attn_mma_k, cudaFuncAttributeMaxDynamicSharedMemorySize, HID_SMEM);

    // weight conversions + combined second-layer bias, one launch
    wcvt_k<<<4866, 256>>>(qk_w, v_w, f1w1, f2w1, f1w2, f2w2,
                          WQK, WV, W11, W21, WCAT, f1b2, f2b2, BC);
    l2norm_src_k<<<NTOK, 128>>>(src, S1h, SRCh);
    // projections: QK + V in one dual launch
    {
        Gp pqk = { S1h, WQK, qk_b, QKh, nullptr, nullptr, nullptr, 1024, 1024, 512, 8 };
        Gp pv  = { SRCh, WV, v_b, Vh, nullptr, nullptr, nullptr, 512, 512, 512, 4 };
        hgemm_dual_k<3><<<192 * 8 + 192 * 4, 256, GSM>>>(pqk, pv, 192 * 8);
    }
    // decay scan -> q1, k1 (half, head-major); one thread per channel
    decay_k<<<dim3(G, 2), 512>>>(QKh, alpha, Q1h, K1h);
    // attentions (fp16 mma, half I/O)
    tok_attn_mma_k<<<1024, 256, TOK_SMEM>>>(Q1h, K1h, Vh, OTr);
    hid_attn_mma_k<<<1024, 256, HID_SMEM>>>(QKh, Vh, OHr);
    // BN stats for both attention outputs, both finals, both weight folds
    bn_partial2_h_k<<<dim3(192, 2), 512>>>(OTr, OHr, PS, PQ, PS2, PQ2);
    bn_final2_k<<<128, 256>>>(PS, PQ, g_pre2, b_pre2, SC1, SH1,
                              PS2, PQ2, g_pre1, b_pre1, SC2, SH2);
    wfold2_k<<<512, 256>>>(W11, f1b1, W21, f2b1, SC1, SH1, SC2, SH2,
                           WF1, BF1, WF2, BF2);
    // FF first layers -> combined hidden [24576, 4096], one dual launch
    {
        Gp p1 = { OTr, WF1, BF1, HBh, nullptr, nullptr, nullptr, 2048, 4096, 512, 16 };
        Gp p2 = { OHr, WF2, BF2, HBh + 2048, nullptr, nullptr, nullptr, 2048, 4096, 512, 16 };
        hgemm_dual_k<1><<<192 * 32, 256, GSM>>>(p1, p2, 192 * 16);
    }
    // combined FF second layer: ACC = HB @ WCAT^T + BC + src, with fused BN partials
    {
        Gp pc = { HBh, WCAT, BC, ACC, src, PS, PQ, 512, 512, 4096, 4 };
        hgemm_k<4><<<192 * 4, 256, GSM>>>(pc);
    }
    // final BN(ACC) -> out (partials already produced by EPI-4 epilogue)
    bn_final_k<<<64, 256>>>(PS, PQ, g_attn, b_attn, SC1, SH1);
    bn_apply1_k<<<NELEM / 4 / 256, 256>>>(out, ACC, SC1, SH1);
}